// round 6
// baseline (speedup 1.0000x reference)
#include <cuda_runtime.h>

// Problem constants (fixed by the dataset's setup_inputs)
#define L_Q        16
#define D_MODEL    1024
#define H_HEADS    16
#define HD         64
#define BS_TOK     16
#define NB_BLOCKS  1024
#define START_POS  16368
#define T_TOTAL    16384
#define SCALE_F    0.125f   // 1/sqrt(64)

// Attention tiling
#define NC       32          // number of KV chunks (split-KV)
#define CHUNK    512         // tokens per chunk
#define TB       128         // tokens per smem tile
#define NTILES   (CHUNK/TB)
#define NBLK     (CHUNK/BS_TOK)   // 32 token-blocks per chunk

// floats: Ks + Vs + Ps + Qs + m/l/c + table (2*32 ptrs = 128 floats, 32 ints = 32)
#define ATTN_SMEM_FLOATS (TB*65 + TB*64 + 16*TB + 16*64 + 48 + 160)
#define ATTN_SMEM_BYTES  (ATTN_SMEM_FLOATS * 4)

// ---------------- device scratch (no allocations allowed) ----------------
__device__ float g_qkv[L_Q * 3 * D_MODEL];            // [16][3072]
__device__ float g_part[H_HEADS * NC * L_Q * HD];     // per-chunk partial O
__device__ float g_m[H_HEADS * NC * L_Q];             // per-chunk running max
__device__ float g_s[H_HEADS * NC * L_Q];             // per-chunk running sumexp
__device__ float g_ao[L_Q * D_MODEL];                 // attention output [16][1024]

// block_ids may arrive as int32 (JAX x64-disabled) or int64. Sniff on device:
// viewed as int32, an int64 array of small non-negative ids has 0 at every odd
// index (little-endian high words); int32 arange-like content has ids[1]!=0.
__device__ __forceinline__ int load_block_id(const void* bi, int blk_idx, int is64) {
    int v;
    if (is64) v = (int)((const long long*)bi)[blk_idx];
    else      v = ((const int*)bi)[blk_idx];
    return v & (NB_BLOCKS - 1);   // memory-safety clamp (no-op for valid ids)
}

__device__ __forceinline__ int sniff_is64(const void* bi) {
    const int* b32 = (const int*)bi;
    return (b32[1] == 0 && b32[3] == 0 && b32[5] == 0 && b32[7] == 0) ? 1 : 0;
}

// ---------------- init: bias-seed qkv and d_out ----------------
__global__ void init_kernel(const float* __restrict__ b_attn,
                            const float* __restrict__ b_proj,
                            float* __restrict__ out) {
    int idx = blockIdx.x * blockDim.x + threadIdx.x;
    if (idx < L_Q * 3 * D_MODEL) g_qkv[idx] = b_attn[idx % (3 * D_MODEL)];
    if (idx < L_Q * D_MODEL)     out[idx]   = b_proj[idx & (D_MODEL - 1)];
}

// ---------------- QKV GEMM: qkv += x @ W_attn (split-K atomics) ----------------
// grid (24, 8) = (j-tiles of 128, i-chunks of 128), 128 threads
__global__ void gemm_qkv(const float* __restrict__ x, const float* __restrict__ W) {
    __shared__ float xs[L_Q][128];
    const int tid = threadIdx.x;
    const int i0 = blockIdx.y * 128;
    for (int idx = tid; idx < L_Q * 128; idx += 128) {
        int l = idx >> 7, ii = idx & 127;
        xs[l][ii] = x[l * D_MODEL + i0 + ii];
    }
    __syncthreads();
    const int j = blockIdx.x * 128 + tid;
    float acc[L_Q] = {};
    #pragma unroll 16
    for (int ii = 0; ii < 128; ii++) {
        float w = W[(long)(i0 + ii) * (3 * D_MODEL) + j];
        #pragma unroll
        for (int l = 0; l < L_Q; l++) acc[l] = fmaf(xs[l][ii], w, acc[l]);
    }
    #pragma unroll
    for (int l = 0; l < L_Q; l++) atomicAdd(&g_qkv[l * (3 * D_MODEL) + j], acc[l]);
}

// ---------------- attention partial (split-KV, online softmax) ----------------
// grid (NC, H), 128 threads, dynamic smem
__global__ void attn_kernel(const float* __restrict__ k_pool,
                            const float* __restrict__ v_pool,
                            const void*  __restrict__ block_ids) {
    extern __shared__ float smem[];
    float* Ks   = smem;                 // [TB][65]  (pad 65: stride-65 scalar LDS conflict-free)
    float* Vs   = Ks + TB * 65;         // [TB][64]
    float* Ps   = Vs + TB * 64;         // [16][TB]  scores -> probabilities
    float* Qs   = Ps + 16 * TB;         // [16][64]  pre-scaled q
    float* sm_m = Qs + 16 * 64;         // [16]
    float* sm_l = sm_m + 16;            // [16]
    float* sm_c = sm_l + 16;            // [16]
    // paged-address table: per 16-token block of this chunk
    const float** kbT = (const float**)(sm_c + 16);        // [32] K row-0 pointers
    const float** vbT = kbT + NBLK;                        // [32] V row-0 pointers
    int*          stT = (int*)(vbT + NBLK);                // [32] row stride (floats)

    const int h     = blockIdx.y;
    const int cidx  = blockIdx.x;
    const int cbase = cidx * CHUNK;
    const int tid   = threadIdx.x;

    for (int idx = tid; idx < 16 * 64; idx += 128) {
        int l = idx >> 6, j = idx & 63;
        Qs[idx] = g_qkv[l * (3 * D_MODEL) + h * HD + j] * SCALE_F;
    }
    if (tid < 16) { sm_m[tid] = -1e30f; sm_l[tid] = 0.f; }

    // Build the per-chunk translation table (absorbs block_ids chain + branch)
    if (tid < NBLK) {
        const int is64 = sniff_is64(block_ids);
        int tok0 = cbase + tid * BS_TOK;
        const float *kb, *vb; int st;
        if (tok0 < START_POS) {
            int blk = load_block_id(block_ids, tok0 >> 4, is64);
            long long base = (long long)blk * (BS_TOK * H_HEADS * HD) + h * HD;
            kb = k_pool + base;
            vb = v_pool + base;
            st = H_HEADS * HD;
        } else {
            int l0 = tok0 - START_POS;
            kb = g_qkv + l0 * (3 * D_MODEL) + D_MODEL     + h * HD;
            vb = g_qkv + l0 * (3 * D_MODEL) + 2 * D_MODEL + h * HD;
            st = 3 * D_MODEL;
        }
        kbT[tid] = kb; vbT[tid] = vb; stT[tid] = st;
    }

    // role decompositions
    const int qkw = tid >> 5;        // QK: query-group (4 queries), lanes = tokens
    const int tg  = tid & 31;
    const int th  = tid >> 6;        // PV: token half
    const int rr  = tid & 63;
    const int lg  = rr >> 4;         // PV: query-group
    const int jg  = rr & 15;         // PV: d-group (4 cols)
    const int sq  = tid >> 3;        // softmax: query
    const int sub = tid & 7;         // softmax: 8 lanes per query (within one warp)

    float o[4][4] = {};
    __syncthreads();

    for (int tile = 0; tile < NTILES; tile++) {
        const int t0 = cbase + tile * TB;

        // ---- load K/V tile: branch-free, fully unrolled -> 32 LDG.128 in flight ----
        #pragma unroll
        for (int it = 0; it < (TB * 16) / 128; it++) {
            int idx = it * 128 + tid;
            int tt  = idx >> 4;               // token within tile
            int f   = (idx & 15) << 2;        // float4 column
            int b   = (tile * TB + tt) >> 4;  // block within chunk
            int off = tt & (BS_TOK - 1);      // row within block (t0 % 16 == 0)
            int rbase = off * stT[b] + f;
            float4 kv = *(const float4*)(kbT[b] + rbase);
            float4 vv = *(const float4*)(vbT[b] + rbase);
            float* kd = Ks + tt * 65 + f;
            kd[0] = kv.x; kd[1] = kv.y; kd[2] = kv.z; kd[3] = kv.w;
            *(float4*)(Vs + tt * 64 + f) = vv;
        }
        __syncthreads();

        // ---- QK: thread computes 4 tokens x 4 queries (16 accs) ----
        {
            float acc[4][4] = {};
            #pragma unroll 4
            for (int j = 0; j < 64; j++) {
                float kk[4], qq[4];
                #pragma unroll
                for (int ti = 0; ti < 4; ti++) kk[ti] = Ks[(tg + 32 * ti) * 65 + j];
                #pragma unroll
                for (int li = 0; li < 4; li++) qq[li] = Qs[(qkw * 4 + li) * 64 + j];
                #pragma unroll
                for (int ti = 0; ti < 4; ti++)
                    #pragma unroll
                    for (int li = 0; li < 4; li++)
                        acc[ti][li] = fmaf(kk[ti], qq[li], acc[ti][li]);
            }
            #pragma unroll
            for (int ti = 0; ti < 4; ti++) {
                int t = t0 + tg + 32 * ti;
                #pragma unroll
                for (int li = 0; li < 4; li++) {
                    int l = qkw * 4 + li;
                    float s = acc[ti][li];
                    if (t > START_POS + l) s = -1e30f;   // causal mask (only last block hits)
                    Ps[l * TB + tg + 32 * ti] = s;
                }
            }
        }
        __syncthreads();

        // ---- online softmax: 8 lanes per query (lane groups within one warp) ----
        {
            float oldm = sm_m[sq];
            float vals[16];
            float tmax = -1e30f;
            #pragma unroll
            for (int k = 0; k < 16; k++) {
                float v = Ps[sq * TB + sub + 8 * k];
                vals[k] = v;
                tmax = fmaxf(tmax, v);
            }
            tmax = fmaxf(tmax, __shfl_xor_sync(0xffffffffu, tmax, 1));
            tmax = fmaxf(tmax, __shfl_xor_sync(0xffffffffu, tmax, 2));
            tmax = fmaxf(tmax, __shfl_xor_sync(0xffffffffu, tmax, 4));
            float newm = fmaxf(oldm, tmax);
            float lsum = 0.f;
            #pragma unroll
            for (int k = 0; k < 16; k++) {
                float p = __expf(vals[k] - newm);
                Ps[sq * TB + sub + 8 * k] = p;
                lsum += p;
            }
            lsum += __shfl_xor_sync(0xffffffffu, lsum, 1);
            lsum += __shfl_xor_sync(0xffffffffu, lsum, 2);
            lsum += __shfl_xor_sync(0xffffffffu, lsum, 4);
            if (sub == 0) {
                float corr = __expf(oldm - newm);
                sm_c[sq] = corr;
                sm_m[sq] = newm;
                sm_l[sq] = sm_l[sq] * corr + lsum;
            }
        }
        __syncthreads();

        // ---- PV: thread accumulates 4 queries x 4 cols over its 64-token half ----
        {
            float corr[4];
            #pragma unroll
            for (int i = 0; i < 4; i++) corr[i] = sm_c[lg * 4 + i];
            #pragma unroll
            for (int i = 0; i < 4; i++)
                #pragma unroll
                for (int j = 0; j < 4; j++) o[i][j] *= corr[i];

            #pragma unroll 4
            for (int t = 0; t < 64; t++) {
                int tt = th * 64 + t;
                float pp[4];
                #pragma unroll
                for (int i = 0; i < 4; i++) pp[i] = Ps[(lg * 4 + i) * TB + tt];
                float4 v = *(const float4*)(Vs + tt * 64 + (jg << 2));
                #pragma unroll
                for (int i = 0; i < 4; i++) {
                    o[i][0] = fmaf(pp[i], v.x, o[i][0]);
                    o[i][1] = fmaf(pp[i], v.y, o[i][1]);
                    o[i][2] = fmaf(pp[i], v.z, o[i][2]);
                    o[i][3] = fmaf(pp[i], v.w, o[i][3]);
                }
            }
        }
        __syncthreads();
    }

    // ---- reduce the two token-halves and write partials ----
    float* red = Ps;  // reuse (>= 1024 floats)
    if (th == 1) {
        #pragma unroll
        for (int i = 0; i < 4; i++)
            #pragma unroll
            for (int j = 0; j < 4; j++) red[rr * 16 + i * 4 + j] = o[i][j];
    }
    __syncthreads();
    if (th == 0) {
        const int pbase = (h * NC + cidx) * L_Q;
        #pragma unroll
        for (int i = 0; i < 4; i++) {
            int l = lg * 4 + i;
            #pragma unroll
            for (int j = 0; j < 4; j++) {
                float val = o[i][j] + red[rr * 16 + i * 4 + j];
                g_part[(pbase + l) * HD + (jg << 2) + j] = val;
            }
        }
    }
    if (tid < 16) {
        int pidx = (h * NC + cidx) * L_Q + tid;
        g_m[pidx] = sm_m[tid];
        g_s[pidx] = sm_l[tid];
    }
}

// ---------------- combine split-KV partials ----------------
// grid (H, L), 64 threads: thread j combines one output element over 32 chunks
__global__ void combine_kernel() {
    const int h = blockIdx.x;
    const int l = blockIdx.y;
    const int j = threadIdx.x;

    // every thread redundantly computes the 32 chunk weights (broadcast loads)
    float m_c[NC];
    float M = -1e30f;
    #pragma unroll
    for (int c = 0; c < NC; c++) {
        m_c[c] = g_m[(h * NC + c) * L_Q + l];
        M = fmaxf(M, m_c[c]);
    }
    float w[NC];
    float S = 0.f;
    #pragma unroll
    for (int c = 0; c < NC; c++) {
        w[c] = __expf(m_c[c] - M);
        S += g_s[(h * NC + c) * L_Q + l] * w[c];
    }
    float acc = 0.f;
    #pragma unroll
    for (int c = 0; c < NC; c++)
        acc += g_part[((h * NC + c) * L_Q + l) * HD + j] * w[c];
    g_ao[l * D_MODEL + h * HD + j] = acc / S;
}

// ---------------- output projection: out += g_ao @ W_proj ----------------
// grid (8, 8), 128 threads
__global__ void gemm_proj(const float* __restrict__ W, float* __restrict__ out) {
    __shared__ float as[L_Q][128];
    const int tid = threadIdx.x;
    const int i0 = blockIdx.y * 128;
    for (int idx = tid; idx < L_Q * 128; idx += 128) {
        int l = idx >> 7, ii = idx & 127;
        as[l][ii] = g_ao[l * D_MODEL + i0 + ii];
    }
    __syncthreads();
    const int j = blockIdx.x * 128 + tid;
    float acc[L_Q] = {};
    #pragma unroll 16
    for (int ii = 0; ii < 128; ii++) {
        float w = W[(long)(i0 + ii) * D_MODEL + j];
        #pragma unroll
        for (int l = 0; l < L_Q; l++) acc[l] = fmaf(as[l][ii], w, acc[l]);
    }
    #pragma unroll
    for (int l = 0; l < L_Q; l++) atomicAdd(&out[l * D_MODEL + j], acc[l]);
}

// ---------------- launch ----------------
extern "C" void kernel_launch(void* const* d_in, const int* in_sizes, int n_in,
                              void* d_out, int out_size) {
    const float* x       = (const float*)d_in[0];
    const float* k_pool  = (const float*)d_in[1];
    const float* v_pool  = (const float*)d_in[2];
    const float* W_attn  = (const float*)d_in[3];
    const float* b_attn  = (const float*)d_in[4];
    const float* W_proj  = (const float*)d_in[5];
    const float* b_proj  = (const float*)d_in[6];
    const void*  blk_ids = (const void*)d_in[7];
    float* out = (float*)d_out;

    static int attr_set = 0;
    if (!attr_set) {
        cudaFuncSetAttribute(attn_kernel, cudaFuncAttributeMaxDynamicSharedMemorySize,
                             ATTN_SMEM_BYTES);
        attr_set = 1;
    }

    init_kernel<<<(L_Q * 3 * D_MODEL + 255) / 256, 256>>>(b_attn, b_proj, out);
    gemm_qkv<<<dim3(24, 8), 128>>>(x, W_attn);
    attn_kernel<<<dim3(NC, H_HEADS), 128, ATTN_SMEM_BYTES>>>(k_pool, v_pool, blk_ids);
    combine_kernel<<<dim3(H_HEADS, L_Q), 64>>>();
    gemm_proj<<<dim3(8, 8), 128>>>(W_proj, out);
}

// round 7
// speedup vs baseline: 1.5457x; 1.5457x over previous
#include <cuda_runtime.h>

// Problem constants (fixed by the dataset's setup_inputs)
#define L_Q        16
#define D_MODEL    1024
#define H_HEADS    16
#define HD         64
#define BS_TOK     16
#define NB_BLOCKS  1024
#define START_POS  16368
#define T_TOTAL    16384
#define SCALE_F    0.125f   // 1/sqrt(64)

// Attention tiling
#define NC       32          // number of KV chunks (split-KV)
#define CHUNK    512         // tokens per chunk
#define TB       64          // tokens per smem tile
#define NTILES   (CHUNK/TB)  // 8
#define KSTRIDE  68          // K smem row stride (f4-aligned, conflict-free)

// ---------------- device scratch (no allocations allowed) ----------------
__device__ float g_qkv[L_Q * 3 * D_MODEL];            // [16][3072]
__device__ float g_part[H_HEADS * NC * L_Q * HD];     // per-chunk partial O
__device__ float g_m[H_HEADS * NC * L_Q];             // per-chunk running max
__device__ float g_s[H_HEADS * NC * L_Q];             // per-chunk running sumexp

// block_ids may arrive as int32 (JAX x64-disabled) or int64. Sniff on device.
__device__ __forceinline__ int load_block_id(const void* bi, int blk_idx, int is64) {
    int v;
    if (is64) v = (int)((const long long*)bi)[blk_idx];
    else      v = ((const int*)bi)[blk_idx];
    return v & (NB_BLOCKS - 1);   // memory-safety clamp (no-op for valid ids)
}
__device__ __forceinline__ int sniff_is64(const void* bi) {
    const int* b32 = (const int*)bi;
    return (b32[1] == 0 && b32[3] == 0 && b32[5] == 0 && b32[7] == 0) ? 1 : 0;
}

// base pointers + row stride for one 16-token block (uniform per warp-iteration)
__device__ __forceinline__ void block_base(const float* __restrict__ kp,
                                           const float* __restrict__ vp,
                                           const void* bi, int is64, int bg, int h,
                                           const float*& kb, const float*& vb, int& st) {
    if (bg < (START_POS / BS_TOK)) {
        int blk = load_block_id(bi, bg, is64);
        long long base = (long long)blk * (BS_TOK * H_HEADS * HD) + h * HD;
        kb = kp + base; vb = vp + base; st = H_HEADS * HD;
    } else {
        int l0 = bg * BS_TOK - START_POS;   // 0 (single tail block)
        kb = g_qkv + l0 * (3 * D_MODEL) + D_MODEL     + h * HD;
        vb = g_qkv + l0 * (3 * D_MODEL) + 2 * D_MODEL + h * HD;
        st = 3 * D_MODEL;
    }
}

// ---------------- init: bias-seed qkv and d_out ----------------
__global__ void init_kernel(const float* __restrict__ b_attn,
                            const float* __restrict__ b_proj,
                            float* __restrict__ out) {
    int idx = blockIdx.x * blockDim.x + threadIdx.x;
    if (idx < L_Q * 3 * D_MODEL) g_qkv[idx] = b_attn[idx % (3 * D_MODEL)];
    if (idx < L_Q * D_MODEL)     out[idx]   = b_proj[idx & (D_MODEL - 1)];
}

// ---------------- QKV GEMM: qkv += x @ W_attn (split-K atomics) ----------------
__global__ void gemm_qkv(const float* __restrict__ x, const float* __restrict__ W) {
    __shared__ float xs[L_Q][128];
    const int tid = threadIdx.x;
    const int i0 = blockIdx.y * 128;
    for (int idx = tid; idx < L_Q * 128; idx += 128) {
        int l = idx >> 7, ii = idx & 127;
        xs[l][ii] = x[l * D_MODEL + i0 + ii];
    }
    __syncthreads();
    const int j = blockIdx.x * 128 + tid;
    float acc[L_Q] = {};
    #pragma unroll 16
    for (int ii = 0; ii < 128; ii++) {
        float w = W[(long)(i0 + ii) * (3 * D_MODEL) + j];
        #pragma unroll
        for (int l = 0; l < L_Q; l++) acc[l] = fmaf(xs[l][ii], w, acc[l]);
    }
    #pragma unroll
    for (int l = 0; l < L_Q; l++) atomicAdd(&g_qkv[l * (3 * D_MODEL) + j], acc[l]);
}

// ---------------- attention partial: pipelined split-KV flash decode ----------------
// grid (NC, H), 256 threads. Register double-buffered K/V gather.
__global__ __launch_bounds__(256, 3)
void attn_kernel(const float* __restrict__ k_pool,
                 const float* __restrict__ v_pool,
                 const void*  __restrict__ block_ids) {
    __shared__ float Ks[TB * KSTRIDE];     // [64][68]
    __shared__ float Vs[TB * HD];          // [64][64]
    __shared__ float Ps[16 * TB];          // [16][64]
    __shared__ float Qs[16 * HD];          // [16][64] pre-scaled
    __shared__ float sm_m[16], sm_l[16], sm_c[16];

    const int h     = blockIdx.y;
    const int cidx  = blockIdx.x;
    const int cbase = cidx * CHUNK;
    const int tid   = threadIdx.x;
    const int is64  = sniff_is64(block_ids);

    for (int idx = tid; idx < 16 * HD; idx += 256) {
        int l = idx >> 6, j = idx & 63;
        Qs[idx] = g_qkv[l * (3 * D_MODEL) + h * HD + j] * SCALE_F;
    }
    if (tid < 16) { sm_m[tid] = -1e30f; sm_l[tid] = 0.f; sm_c[tid] = 0.f; }

    // role decompositions
    const int off = tid >> 4;          // load: row within 16-token block (0..15)
    const int f   = (tid & 15) << 2;   // load/PV: float4 column
    const int tok = tid & 63;          // QK: token
    const int qg  = tid >> 6;          // QK: query group (4 queries)
    const int pq  = tid >> 4;          // PV: query (0..15)
    const int wrp = tid >> 5, lane = tid & 31;

    float4 kreg[4], vreg[4];

    // prologue: gather tile 0 into registers (8 independent LDG.128)
    {
        const int nb = cbase >> 4;
        #pragma unroll
        for (int k = 0; k < 4; k++) {
            const float *kb, *vb; int st;
            block_base(k_pool, v_pool, block_ids, is64, nb + k, h, kb, vb, st);
            kreg[k] = *(const float4*)(kb + off * st + f);
            vreg[k] = *(const float4*)(vb + off * st + f);
        }
    }

    float o0 = 0.f, o1 = 0.f, o2 = 0.f, o3 = 0.f;

    for (int tile = 0; tile < NTILES; tile++) {
        __syncthreads();   // previous tile's consumers done (also covers Qs on tile 0)

        // stage registers -> smem
        #pragma unroll
        for (int k = 0; k < 4; k++) {
            int tt = k * 16 + off;
            *(float4*)&Ks[tt * KSTRIDE + f] = kreg[k];
            *(float4*)&Vs[tt * HD + f]      = vreg[k];
        }

        // prefetch next tile (loads in flight across the whole compute phase)
        if (tile < NTILES - 1) {
            const int nb = (cbase >> 4) + (tile + 1) * 4;
            #pragma unroll
            for (int k = 0; k < 4; k++) {
                const float *kb, *vb; int st;
                block_base(k_pool, v_pool, block_ids, is64, nb + k, h, kb, vb, st);
                kreg[k] = *(const float4*)(kb + off * st + f);
                vreg[k] = *(const float4*)(vb + off * st + f);
            }
        }
        __syncthreads();   // tile data visible

        // ---- QK: thread -> (token, 4 queries) ----
        {
            float a0 = 0.f, a1 = 0.f, a2 = 0.f, a3 = 0.f;
            #pragma unroll
            for (int j4 = 0; j4 < 16; j4++) {
                float4 kk = *(const float4*)&Ks[tok * KSTRIDE + j4 * 4];
                float4 q0 = *(const float4*)&Qs[(qg * 4 + 0) * HD + j4 * 4];
                float4 q1 = *(const float4*)&Qs[(qg * 4 + 1) * HD + j4 * 4];
                float4 q2 = *(const float4*)&Qs[(qg * 4 + 2) * HD + j4 * 4];
                float4 q3 = *(const float4*)&Qs[(qg * 4 + 3) * HD + j4 * 4];
                a0 = fmaf(kk.x, q0.x, fmaf(kk.y, q0.y, fmaf(kk.z, q0.z, fmaf(kk.w, q0.w, a0))));
                a1 = fmaf(kk.x, q1.x, fmaf(kk.y, q1.y, fmaf(kk.z, q1.z, fmaf(kk.w, q1.w, a1))));
                a2 = fmaf(kk.x, q2.x, fmaf(kk.y, q2.y, fmaf(kk.z, q2.z, fmaf(kk.w, q2.w, a2))));
                a3 = fmaf(kk.x, q3.x, fmaf(kk.y, q3.y, fmaf(kk.z, q3.z, fmaf(kk.w, q3.w, a3))));
            }
            const int t0 = cbase + tile * TB;
            const int t  = t0 + tok;
            if (t0 + TB - 1 > START_POS) {   // only last tile of last chunk
                if (t > START_POS + qg * 4 + 0) a0 = -1e30f;
                if (t > START_POS + qg * 4 + 1) a1 = -1e30f;
                if (t > START_POS + qg * 4 + 2) a2 = -1e30f;
                if (t > START_POS + qg * 4 + 3) a3 = -1e30f;
            }
            Ps[(qg * 4 + 0) * TB + tok] = a0;
            Ps[(qg * 4 + 1) * TB + tok] = a1;
            Ps[(qg * 4 + 2) * TB + tok] = a2;
            Ps[(qg * 4 + 3) * TB + tok] = a3;
        }
        __syncthreads();

        // ---- online softmax: warp w handles queries 2w, 2w+1 ----
        #pragma unroll
        for (int qi = 0; qi < 2; qi++) {
            int q = wrp * 2 + qi;
            float v0 = Ps[q * TB + lane];
            float v1 = Ps[q * TB + 32 + lane];
            float mx = fmaxf(v0, v1);
            #pragma unroll
            for (int s = 16; s >= 1; s >>= 1) mx = fmaxf(mx, __shfl_xor_sync(0xffffffffu, mx, s));
            float oldm = sm_m[q];
            float nm = fmaxf(oldm, mx);
            float e0 = __expf(v0 - nm), e1 = __expf(v1 - nm);
            Ps[q * TB + lane]      = e0;
            Ps[q * TB + 32 + lane] = e1;
            float ls = e0 + e1;
            #pragma unroll
            for (int s = 16; s >= 1; s >>= 1) ls += __shfl_xor_sync(0xffffffffu, ls, s);
            if (lane == 0) {
                float cr = __expf(oldm - nm);
                sm_c[q] = cr;
                sm_m[q] = nm;
                sm_l[q] = sm_l[q] * cr + ls;
            }
        }
        __syncthreads();

        // ---- PV: thread -> (query pq, 4 cols f..f+3) ----
        {
            float cr = sm_c[pq];
            o0 *= cr; o1 *= cr; o2 *= cr; o3 *= cr;
            #pragma unroll
            for (int t4 = 0; t4 < 16; t4++) {
                float4 p  = *(const float4*)&Ps[pq * TB + t4 * 4];
                float4 va = *(const float4*)&Vs[(t4 * 4 + 0) * HD + f];
                float4 vb = *(const float4*)&Vs[(t4 * 4 + 1) * HD + f];
                float4 vc = *(const float4*)&Vs[(t4 * 4 + 2) * HD + f];
                float4 vd = *(const float4*)&Vs[(t4 * 4 + 3) * HD + f];
                o0 = fmaf(p.x, va.x, fmaf(p.y, vb.x, fmaf(p.z, vc.x, fmaf(p.w, vd.x, o0))));
                o1 = fmaf(p.x, va.y, fmaf(p.y, vb.y, fmaf(p.z, vc.y, fmaf(p.w, vd.y, o1))));
                o2 = fmaf(p.x, va.z, fmaf(p.y, vb.z, fmaf(p.z, vc.z, fmaf(p.w, vd.z, o2))));
                o3 = fmaf(p.x, va.w, fmaf(p.y, vb.w, fmaf(p.z, vc.w, fmaf(p.w, vd.w, o3))));
            }
        }
    }
    __syncthreads();

    // ---- write partials (each thread owns its 4 output elements) ----
    const int pbase = (h * NC + cidx) * L_Q;
    float4 ov = make_float4(o0, o1, o2, o3);
    *(float4*)&g_part[(pbase + pq) * HD + f] = ov;
    if (tid < 16) {
        g_m[pbase + tid] = sm_m[tid];
        g_s[pbase + tid] = sm_l[tid];
    }
}

// ---------------- fused combine + output projection ----------------
// grid (8, 8), 128 threads. Block (bx,by): out cols bx*128.., a-rows i0=by*128 (2 heads).
__global__ void gemm_proj(const float* __restrict__ W, float* __restrict__ out) {
    __shared__ float as[L_Q][128];
    __shared__ float w_s[2][L_Q][NC];
    __shared__ float S_s[2][L_Q];
    const int tid = threadIdx.x;
    const int i0 = blockIdx.y * 128;
    const int h0 = i0 >> 6;          // first of the 2 heads this block combines

    // phase A: softmax-merge weights for the 2 heads x 16 queries
    if (tid < 32) {
        int hh = tid >> 4, l = tid & 15;
        int h = h0 + hh;
        float m[NC]; float M = -1e30f;
        #pragma unroll
        for (int c = 0; c < NC; c++) { m[c] = g_m[(h * NC + c) * L_Q + l]; M = fmaxf(M, m[c]); }
        float S = 0.f;
        #pragma unroll
        for (int c = 0; c < NC; c++) {
            float w = __expf(m[c] - M);
            w_s[hh][l][c] = w;
            S += g_s[(h * NC + c) * L_Q + l] * w;
        }
        S_s[hh][l] = S;
    }
    __syncthreads();

    // phase B: combine partials into the a-tile
    {
        int hh = tid >> 6, j = tid & 63;
        int h = h0 + hh;
        for (int l = 0; l < L_Q; l++) {
            float acc = 0.f;
            #pragma unroll
            for (int c = 0; c < NC; c++)
                acc += g_part[((h * NC + c) * L_Q + l) * HD + j] * w_s[hh][l][c];
            as[l][hh * 64 + j] = acc / S_s[hh][l];
        }
    }
    __syncthreads();

    // phase C: out += a_tile @ W_proj[i0:i0+128, :]
    const int j = blockIdx.x * 128 + tid;
    float acc[L_Q] = {};
    #pragma unroll 16
    for (int ii = 0; ii < 128; ii++) {
        float w = W[(long)(i0 + ii) * D_MODEL + j];
        #pragma unroll
        for (int l = 0; l < L_Q; l++) acc[l] = fmaf(as[l][ii], w, acc[l]);
    }
    #pragma unroll
    for (int l = 0; l < L_Q; l++) atomicAdd(&out[l * D_MODEL + j], acc[l]);
}

// ---------------- launch ----------------
extern "C" void kernel_launch(void* const* d_in, const int* in_sizes, int n_in,
                              void* d_out, int out_size) {
    const float* x       = (const float*)d_in[0];
    const float* k_pool  = (const float*)d_in[1];
    const float* v_pool  = (const float*)d_in[2];
    const float* W_attn  = (const float*)d_in[3];
    const float* b_attn  = (const float*)d_in[4];
    const float* W_proj  = (const float*)d_in[5];
    const float* b_proj  = (const float*)d_in[6];
    const void*  blk_ids = (const void*)d_in[7];
    float* out = (float*)d_out;

    init_kernel<<<(L_Q * 3 * D_MODEL + 255) / 256, 256>>>(b_attn, b_proj, out);
    gemm_qkv<<<dim3(24, 8), 128>>>(x, W_attn);
    attn_kernel<<<dim3(NC, H_HEADS), 256>>>(k_pool, v_pool, blk_ids);
    gemm_proj<<<dim3(8, 8), 128>>>(W_proj, out);
}

// round 8
// speedup vs baseline: 1.9756x; 1.2781x over previous
#include <cuda_runtime.h>

// Problem constants (fixed by the dataset's setup_inputs)
#define L_Q        16
#define D_MODEL    1024
#define H_HEADS    16
#define HD         64
#define BS_TOK     16
#define NB_BLOCKS  1024
#define START_POS  16368
#define T_TOTAL    16384
#define SCALE_F    0.125f   // 1/sqrt(64)

// Attention tiling
#define NC       32          // number of KV chunks (split-KV)
#define CHUNK    512         // tokens per chunk
#define TB       64          // tokens per smem tile
#define NTILES   (CHUNK/TB)  // 8
#define KSTRIDE  68          // K smem row stride floats (16B-aligned rows, conflict-free)

typedef unsigned long long ull;

// ---------------- f32x2 packed math (FFMA2: ptxas never emits this from C++) ----
__device__ __forceinline__ ull ffma2(ull a, ull b, ull c) {
    ull d;
    asm("fma.rn.f32x2 %0, %1, %2, %3;" : "=l"(d) : "l"(a), "l"(b), "l"(c));
    return d;
}
__device__ __forceinline__ ull fmul2(ull a, ull b) {
    ull d;
    asm("mul.rn.f32x2 %0, %1, %2;" : "=l"(d) : "l"(a), "l"(b));
    return d;
}
__device__ __forceinline__ ull pack2(float x, float y) {
    ull r;
    asm("mov.b64 %0, {%1, %2};" : "=l"(r) : "f"(x), "f"(y));
    return r;
}
__device__ __forceinline__ float2 unpack2(ull v) {
    float x, y;
    asm("mov.b64 {%0, %1}, %2;" : "=f"(x), "=f"(y) : "l"(v));
    return make_float2(x, y);
}

// ---------------- device scratch (no allocations allowed) ----------------
__device__ float g_qkv[L_Q * 3 * D_MODEL];            // [16][3072]
__device__ float g_part[H_HEADS * NC * L_Q * HD];     // per-chunk partial O
__device__ float g_m[H_HEADS * NC * L_Q];             // per-chunk running max
__device__ float g_s[H_HEADS * NC * L_Q];             // per-chunk running sumexp
__device__ float g_ao[L_Q * D_MODEL];                 // combined attention output

// block_ids may arrive as int32 (JAX x64-disabled) or int64. Sniff on device.
__device__ __forceinline__ int load_block_id(const void* bi, int blk_idx, int is64) {
    int v;
    if (is64) v = (int)((const long long*)bi)[blk_idx];
    else      v = ((const int*)bi)[blk_idx];
    return v & (NB_BLOCKS - 1);   // memory-safety clamp (no-op for valid ids)
}
__device__ __forceinline__ int sniff_is64(const void* bi) {
    const int* b32 = (const int*)bi;
    return (b32[1] == 0 && b32[3] == 0 && b32[5] == 0 && b32[7] == 0) ? 1 : 0;
}

// base pointers + row stride for one 16-token block
__device__ __forceinline__ void block_base(const float* __restrict__ kp,
                                           const float* __restrict__ vp,
                                           const void* bi, int is64, int bg, int h,
                                           const float*& kb, const float*& vb, int& st) {
    if (bg < (START_POS / BS_TOK)) {
        int blk = load_block_id(bi, bg, is64);
        long long base = (long long)blk * (BS_TOK * H_HEADS * HD) + h * HD;
        kb = kp + base; vb = vp + base; st = H_HEADS * HD;
    } else {
        int l0 = bg * BS_TOK - START_POS;   // 0 (single tail block)
        kb = g_qkv + l0 * (3 * D_MODEL) + D_MODEL     + h * HD;
        vb = g_qkv + l0 * (3 * D_MODEL) + 2 * D_MODEL + h * HD;
        st = 3 * D_MODEL;
    }
}

// ---------------- init: bias-seed qkv and d_out ----------------
__global__ void init_kernel(const float* __restrict__ b_attn,
                            const float* __restrict__ b_proj,
                            float* __restrict__ out) {
    int idx = blockIdx.x * blockDim.x + threadIdx.x;
    if (idx < L_Q * 3 * D_MODEL) g_qkv[idx] = b_attn[idx % (3 * D_MODEL)];
    if (idx < L_Q * D_MODEL)     out[idx]   = b_proj[idx & (D_MODEL - 1)];
}

// ---------------- QKV GEMM: qkv += x @ W_attn (split-K atomics) ----------------
// grid (24, 16): j-tiles of 128, i-chunks of 64. 128 threads.
__global__ void gemm_qkv(const float* __restrict__ x, const float* __restrict__ W) {
    __shared__ float xs[L_Q][64];
    const int tid = threadIdx.x;
    const int i0 = blockIdx.y * 64;
    for (int idx = tid; idx < L_Q * 64; idx += 128) {
        int l = idx >> 6, ii = idx & 63;
        xs[l][ii] = x[l * D_MODEL + i0 + ii];
    }
    __syncthreads();
    const int j = blockIdx.x * 128 + tid;
    float acc[L_Q] = {};
    #pragma unroll 16
    for (int ii = 0; ii < 64; ii++) {
        float w = W[(long)(i0 + ii) * (3 * D_MODEL) + j];
        #pragma unroll
        for (int l = 0; l < L_Q; l++) acc[l] = fmaf(xs[l][ii], w, acc[l]);
    }
    #pragma unroll
    for (int l = 0; l < L_Q; l++) atomicAdd(&g_qkv[l * (3 * D_MODEL) + j], acc[l]);
}

// ---------------- attention partial: pipelined split-KV flash decode ----------------
// grid (NC, H), 256 threads, 4 CTAs/SM -> single wave of 512 CTAs.
__global__ __launch_bounds__(256, 4)
void attn_kernel(const float* __restrict__ k_pool,
                 const float* __restrict__ v_pool,
                 const void*  __restrict__ block_ids) {
    __shared__ __align__(16) float Ks[TB * KSTRIDE];  // [64][68]
    __shared__ __align__(16) float Vs[TB * HD];       // [64][64]
    __shared__ __align__(16) float Ps[16 * TB];       // [16][64]
    __shared__ __align__(16) float Qs[16 * HD];       // [16][64] pre-scaled
    __shared__ float sm_m[16], sm_l[16], sm_c[16];

    const int h     = blockIdx.y;
    const int cidx  = blockIdx.x;
    const int cbase = cidx * CHUNK;
    const int tid   = threadIdx.x;
    const int is64  = sniff_is64(block_ids);

    for (int idx = tid; idx < 16 * HD; idx += 256) {
        int l = idx >> 6, j = idx & 63;
        Qs[idx] = g_qkv[l * (3 * D_MODEL) + h * HD + j] * SCALE_F;
    }
    if (tid < 16) { sm_m[tid] = -1e30f; sm_l[tid] = 0.f; sm_c[tid] = 0.f; }

    // role decompositions
    const int off = tid >> 4;          // load: row within 16-token block (0..15)
    const int f   = (tid & 15) << 2;   // load/PV: float4 column
    const int tok = tid & 63;          // QK: token
    const int qg  = tid >> 6;          // QK: query group (4 queries)
    const int pq  = tid >> 4;          // PV: query (0..15)
    const int wrp = tid >> 5, lane = tid & 31;

    float4 kreg[4], vreg[4];

    // prologue: gather tile 0 into registers (8 independent LDG.128)
    {
        const int nb = cbase >> 4;
        #pragma unroll
        for (int k = 0; k < 4; k++) {
            const float *kb, *vb; int st;
            block_base(k_pool, v_pool, block_ids, is64, nb + k, h, kb, vb, st);
            kreg[k] = *(const float4*)(kb + off * st + f);
            vreg[k] = *(const float4*)(vb + off * st + f);
        }
    }

    ull o01 = pack2(0.f, 0.f), o23 = o01;

    for (int tile = 0; tile < NTILES; tile++) {
        __syncthreads();   // previous tile's consumers done (also covers Qs on tile 0)

        // stage registers -> smem
        #pragma unroll
        for (int k = 0; k < 4; k++) {
            int tt = k * 16 + off;
            *(float4*)&Ks[tt * KSTRIDE + f] = kreg[k];
            *(float4*)&Vs[tt * HD + f]      = vreg[k];
        }

        // prefetch next tile (loads in flight across the whole compute phase)
        if (tile < NTILES - 1) {
            const int nb = (cbase >> 4) + (tile + 1) * 4;
            #pragma unroll
            for (int k = 0; k < 4; k++) {
                const float *kb, *vb; int st;
                block_base(k_pool, v_pool, block_ids, is64, nb + k, h, kb, vb, st);
                kreg[k] = *(const float4*)(kb + off * st + f);
                vreg[k] = *(const float4*)(vb + off * st + f);
            }
        }
        __syncthreads();   // tile data visible

        // ---- QK (FFMA2): thread -> (token, 4 queries) ----
        {
            ull a0 = pack2(0.f, 0.f), a1 = a0, a2 = a0, a3 = a0;
            const ulonglong2* krow = (const ulonglong2*)&Ks[tok * KSTRIDE];
            const ulonglong2* q0r  = (const ulonglong2*)&Qs[(qg * 4 + 0) * HD];
            const ulonglong2* q1r  = (const ulonglong2*)&Qs[(qg * 4 + 1) * HD];
            const ulonglong2* q2r  = (const ulonglong2*)&Qs[(qg * 4 + 2) * HD];
            const ulonglong2* q3r  = (const ulonglong2*)&Qs[(qg * 4 + 3) * HD];
            #pragma unroll
            for (int j4 = 0; j4 < 16; j4++) {
                ulonglong2 kk = krow[j4];
                ulonglong2 q0 = q0r[j4], q1 = q1r[j4], q2 = q2r[j4], q3 = q3r[j4];
                a0 = ffma2(kk.x, q0.x, ffma2(kk.y, q0.y, a0));
                a1 = ffma2(kk.x, q1.x, ffma2(kk.y, q1.y, a1));
                a2 = ffma2(kk.x, q2.x, ffma2(kk.y, q2.y, a2));
                a3 = ffma2(kk.x, q3.x, ffma2(kk.y, q3.y, a3));
            }
            float2 u0 = unpack2(a0), u1 = unpack2(a1), u2 = unpack2(a2), u3 = unpack2(a3);
            float s0 = u0.x + u0.y, s1 = u1.x + u1.y, s2 = u2.x + u2.y, s3 = u3.x + u3.y;
            const int t0 = cbase + tile * TB;
            const int t  = t0 + tok;
            if (t0 + TB - 1 > START_POS) {   // only last tile of last chunk
                if (t > START_POS + qg * 4 + 0) s0 = -1e30f;
                if (t > START_POS + qg * 4 + 1) s1 = -1e30f;
                if (t > START_POS + qg * 4 + 2) s2 = -1e30f;
                if (t > START_POS + qg * 4 + 3) s3 = -1e30f;
            }
            Ps[(qg * 4 + 0) * TB + tok] = s0;
            Ps[(qg * 4 + 1) * TB + tok] = s1;
            Ps[(qg * 4 + 2) * TB + tok] = s2;
            Ps[(qg * 4 + 3) * TB + tok] = s3;
        }
        __syncthreads();

        // ---- online softmax: warp w handles queries 2w, 2w+1 ----
        #pragma unroll
        for (int qi = 0; qi < 2; qi++) {
            int q = wrp * 2 + qi;
            float v0 = Ps[q * TB + lane];
            float v1 = Ps[q * TB + 32 + lane];
            float mx = fmaxf(v0, v1);
            #pragma unroll
            for (int s = 16; s >= 1; s >>= 1) mx = fmaxf(mx, __shfl_xor_sync(0xffffffffu, mx, s));
            float oldm = sm_m[q];
            float nm = fmaxf(oldm, mx);
            float e0 = __expf(v0 - nm), e1 = __expf(v1 - nm);
            Ps[q * TB + lane]      = e0;
            Ps[q * TB + 32 + lane] = e1;
            float ls = e0 + e1;
            #pragma unroll
            for (int s = 16; s >= 1; s >>= 1) ls += __shfl_xor_sync(0xffffffffu, ls, s);
            if (lane == 0) {
                float cr = __expf(oldm - nm);
                sm_c[q] = cr;
                sm_m[q] = nm;
                sm_l[q] = sm_l[q] * cr + ls;
            }
        }
        __syncthreads();

        // ---- PV (FFMA2): thread -> (query pq, 4 cols f..f+3) ----
        {
            float cr = sm_c[pq];
            ull crp = pack2(cr, cr);
            o01 = fmul2(o01, crp);
            o23 = fmul2(o23, crp);
            const float4* prow = (const float4*)&Ps[pq * TB];
            #pragma unroll
            for (int t4 = 0; t4 < 16; t4++) {
                float4 p = prow[t4];
                ull pa = pack2(p.x, p.x), pb = pack2(p.y, p.y);
                ull pc = pack2(p.z, p.z), pd = pack2(p.w, p.w);
                ulonglong2 va = *(const ulonglong2*)&Vs[(t4 * 4 + 0) * HD + f];
                ulonglong2 vb = *(const ulonglong2*)&Vs[(t4 * 4 + 1) * HD + f];
                ulonglong2 vc = *(const ulonglong2*)&Vs[(t4 * 4 + 2) * HD + f];
                ulonglong2 vd = *(const ulonglong2*)&Vs[(t4 * 4 + 3) * HD + f];
                o01 = ffma2(pa, va.x, o01); o23 = ffma2(pa, va.y, o23);
                o01 = ffma2(pb, vb.x, o01); o23 = ffma2(pb, vb.y, o23);
                o01 = ffma2(pc, vc.x, o01); o23 = ffma2(pc, vc.y, o23);
                o01 = ffma2(pd, vd.x, o01); o23 = ffma2(pd, vd.y, o23);
            }
        }
    }
    __syncthreads();

    // ---- write partials (each thread owns its 4 output elements) ----
    const int pbase = (h * NC + cidx) * L_Q;
    float2 a = unpack2(o01), b = unpack2(o23);
    float4 ov = make_float4(a.x, a.y, b.x, b.y);
    *(float4*)&g_part[(pbase + pq) * HD + f] = ov;
    if (tid < 16) {
        g_m[pbase + tid] = sm_m[tid];
        g_s[pbase + tid] = sm_l[tid];
    }
}

// ---------------- combine split-KV partials ----------------
// grid (H, L), 256 threads: (j = tid&63) x (chunk-group = tid>>6 of 8 chunks)
__global__ void combine_kernel() {
    __shared__ float red[4][64];
    const int h = blockIdx.x;
    const int l = blockIdx.y;
    const int tid = threadIdx.x;
    const int j  = tid & 63;
    const int cg = tid >> 6;

    // all threads compute the 32 merge weights (broadcast loads, L2-hot)
    float m[NC]; float M = -1e30f;
    #pragma unroll
    for (int c = 0; c < NC; c++) { m[c] = g_m[(h * NC + c) * L_Q + l]; M = fmaxf(M, m[c]); }
    float w[NC]; float S = 0.f;
    #pragma unroll
    for (int c = 0; c < NC; c++) {
        w[c] = __expf(m[c] - M);
        S += g_s[(h * NC + c) * L_Q + l] * w[c];
    }

    float acc = 0.f;
    #pragma unroll
    for (int ci = 0; ci < 8; ci++) {
        int c = cg * 8 + ci;
        acc += g_part[((h * NC + c) * L_Q + l) * HD + j] * w[c];
    }
    red[cg][j] = acc;
    __syncthreads();
    if (cg == 0) {
        float tot = red[0][j] + red[1][j] + red[2][j] + red[3][j];
        g_ao[l * D_MODEL + h * HD + j] = tot / S;
    }
}

// ---------------- output projection: out += g_ao @ W_proj (split-K atomics) ----
// grid (8, 16): j-tiles of 128, i-chunks of 64. 128 threads.
__global__ void gemm_proj(const float* __restrict__ W, float* __restrict__ out) {
    __shared__ float as[L_Q][64];
    const int tid = threadIdx.x;
    const int i0 = blockIdx.y * 64;
    for (int idx = tid; idx < L_Q * 64; idx += 128) {
        int l = idx >> 6, ii = idx & 63;
        as[l][ii] = g_ao[l * D_MODEL + i0 + ii];
    }
    __syncthreads();
    const int j = blockIdx.x * 128 + tid;
    float acc[L_Q] = {};
    #pragma unroll 16
    for (int ii = 0; ii < 64; ii++) {
        float w = W[(long)(i0 + ii) * D_MODEL + j];
        #pragma unroll
        for (int l = 0; l < L_Q; l++) acc[l] = fmaf(as[l][ii], w, acc[l]);
    }
    #pragma unroll
    for (int l = 0; l < L_Q; l++) atomicAdd(&out[l * D_MODEL + j], acc[l]);
}

// ---------------- launch ----------------
extern "C" void kernel_launch(void* const* d_in, const int* in_sizes, int n_in,
                              void* d_out, int out_size) {
    const float* x       = (const float*)d_in[0];
    const float* k_pool  = (const float*)d_in[1];
    const float* v_pool  = (const float*)d_in[2];
    const float* W_attn  = (const float*)d_in[3];
    const float* b_attn  = (const float*)d_in[4];
    const float* W_proj  = (const float*)d_in[5];
    const float* b_proj  = (const float*)d_in[6];
    const void*  blk_ids = (const void*)d_in[7];
    float* out = (float*)d_out;

    init_kernel<<<(L_Q * 3 * D_MODEL + 255) / 256, 256>>>(b_attn, b_proj, out);
    gemm_qkv<<<dim3(24, 16), 128>>>(x, W_attn);
    attn_kernel<<<dim3(NC, H_HEADS), 256>>>(k_pool, v_pool, blk_ids);
    combine_kernel<<<dim3(H_HEADS, L_Q), 256>>>();
    gemm_proj<<<dim3(8, 16), 128>>>(W_proj, out);
}

// round 9
// speedup vs baseline: 2.2979x; 1.1631x over previous
#include <cuda_runtime.h>

// Problem constants (fixed by the dataset's setup_inputs)
#define L_Q        16
#define D_MODEL    1024
#define H_HEADS    16
#define HD         64
#define BS_TOK     16
#define NB_BLOCKS  1024
#define START_POS  16368
#define T_TOTAL    16384
#define SCALE_F    0.125f   // 1/sqrt(64)

// Attention tiling
#define NC       16          // number of KV chunks (split-KV)
#define CHUNK    1024        // tokens per chunk
#define TB       64          // tokens per smem tile
#define NTILES   (CHUNK/TB)  // 16
#define KSTRIDE  68          // K smem row stride floats (16B rows, conflict-free f4)

typedef unsigned long long ull;

// ---------------- f32x2 packed math (ptxas never emits FFMA2 from C++) ----------
__device__ __forceinline__ ull ffma2(ull a, ull b, ull c) {
    ull d;
    asm("fma.rn.f32x2 %0, %1, %2, %3;" : "=l"(d) : "l"(a), "l"(b), "l"(c));
    return d;
}
__device__ __forceinline__ ull fmul2(ull a, ull b) {
    ull d;
    asm("mul.rn.f32x2 %0, %1, %2;" : "=l"(d) : "l"(a), "l"(b));
    return d;
}
__device__ __forceinline__ ull fadd2(ull a, ull b) {
    ull d;
    asm("add.rn.f32x2 %0, %1, %2;" : "=l"(d) : "l"(a), "l"(b));
    return d;
}
__device__ __forceinline__ ull pack2(float x, float y) {
    ull r;
    asm("mov.b64 %0, {%1, %2};" : "=l"(r) : "f"(x), "f"(y));
    return r;
}
__device__ __forceinline__ float2 unpack2(ull v) {
    float x, y;
    asm("mov.b64 {%0, %1}, %2;" : "=f"(x), "=f"(y) : "l"(v));
    return make_float2(x, y);
}

// ---------------- device scratch (no allocations allowed) ----------------
__device__ float g_qkv[L_Q * 3 * D_MODEL];            // [16][3072]
__device__ float g_part[H_HEADS * NC * L_Q * HD];     // per-chunk partial O
__device__ float g_m[H_HEADS * NC * L_Q];             // per-chunk running max
__device__ float g_s[H_HEADS * NC * L_Q];             // per-chunk running sumexp
__device__ float g_ao[L_Q * D_MODEL];                 // combined attention output

// block_ids may arrive as int32 (JAX x64-disabled) or int64. Sniff on device.
__device__ __forceinline__ int load_block_id(const void* bi, int blk_idx, int is64) {
    int v;
    if (is64) v = (int)((const long long*)bi)[blk_idx];
    else      v = ((const int*)bi)[blk_idx];
    return v & (NB_BLOCKS - 1);   // memory-safety clamp (no-op for valid ids)
}
__device__ __forceinline__ int sniff_is64(const void* bi) {
    const int* b32 = (const int*)bi;
    return (b32[1] == 0 && b32[3] == 0 && b32[5] == 0 && b32[7] == 0) ? 1 : 0;
}

// base pointers + row stride for one 16-token block
__device__ __forceinline__ void block_base(const float* __restrict__ kp,
                                           const float* __restrict__ vp,
                                           const void* bi, int is64, int bg, int h,
                                           const float*& kb, const float*& vb, int& st) {
    if (bg < (START_POS / BS_TOK)) {
        int blk = load_block_id(bi, bg, is64);
        long long base = (long long)blk * (BS_TOK * H_HEADS * HD) + h * HD;
        kb = kp + base; vb = vp + base; st = H_HEADS * HD;
    } else {
        int l0 = bg * BS_TOK - START_POS;   // 0 (single tail block)
        kb = g_qkv + l0 * (3 * D_MODEL) + D_MODEL     + h * HD;
        vb = g_qkv + l0 * (3 * D_MODEL) + 2 * D_MODEL + h * HD;
        st = 3 * D_MODEL;
    }
}

// ---------------- init: bias-seed qkv and d_out ----------------
__global__ void init_kernel(const float* __restrict__ b_attn,
                            const float* __restrict__ b_proj,
                            float* __restrict__ out) {
    int idx = blockIdx.x * blockDim.x + threadIdx.x;
    if (idx < L_Q * 3 * D_MODEL) g_qkv[idx] = b_attn[idx % (3 * D_MODEL)];
    if (idx < L_Q * D_MODEL)     out[idx]   = b_proj[idx & (D_MODEL - 1)];
}

// ---------------- QKV GEMM: qkv += x @ W_attn (split-K atomics) ----------------
// grid (24, 16): j-tiles of 128, i-chunks of 64. 128 threads.
__global__ void gemm_qkv(const float* __restrict__ x, const float* __restrict__ W) {
    __shared__ float xs[L_Q][64];
    const int tid = threadIdx.x;
    const int i0 = blockIdx.y * 64;
    for (int idx = tid; idx < L_Q * 64; idx += 128) {
        int l = idx >> 6, ii = idx & 63;
        xs[l][ii] = x[l * D_MODEL + i0 + ii];
    }
    __syncthreads();
    const int j = blockIdx.x * 128 + tid;
    float acc[L_Q] = {};
    #pragma unroll 16
    for (int ii = 0; ii < 64; ii++) {
        float w = W[(long)(i0 + ii) * (3 * D_MODEL) + j];
        #pragma unroll
        for (int l = 0; l < L_Q; l++) acc[l] = fmaf(xs[l][ii], w, acc[l]);
    }
    #pragma unroll
    for (int l = 0; l < L_Q; l++) atomicAdd(&g_qkv[l * (3 * D_MODEL) + j], acc[l]);
}

// ---------------- attention partial: pipelined split-KV flash decode ----------------
// grid (NC, H) = 256 CTAs, 256 threads, 2 CTAs/SM -> single wave.
// PV: thread owns (8 queries x 4 cols) over an 8-token slice -> V smem read 2x (was 16x).
__global__ __launch_bounds__(256, 2)
void attn_kernel(const float* __restrict__ k_pool,
                 const float* __restrict__ v_pool,
                 const void*  __restrict__ block_ids) {
    __shared__ __align__(16) float Ks[TB * KSTRIDE];  // [64][68]
    __shared__ __align__(16) float Vs[TB * HD];       // [64][64]
    __shared__ __align__(16) float Ps[16 * TB];       // [16][64]
    __shared__ __align__(16) float Qs[16 * HD];       // [16][64] pre-scaled
    __shared__ float sm_m[16], sm_l[16], sm_c[16];

    const int h     = blockIdx.y;
    const int cidx  = blockIdx.x;
    const int cbase = cidx * CHUNK;
    const int tid   = threadIdx.x;
    const int is64  = sniff_is64(block_ids);

    for (int idx = tid; idx < 16 * HD; idx += 256) {
        int l = idx >> 6, j = idx & 63;
        Qs[idx] = g_qkv[l * (3 * D_MODEL) + h * HD + j] * SCALE_F;
    }
    if (tid < 16) { sm_m[tid] = -1e30f; sm_l[tid] = 0.f; sm_c[tid] = 0.f; }

    // role decompositions
    const int off = tid >> 4;          // load: row within 16-token block (0..15)
    const int fg  = tid & 15;          // col group
    const int f   = fg << 2;           // float4 column
    const int tok = tid & 63;          // QK: token
    const int qg  = tid >> 6;          // QK: query group (4 queries)
    const int wrp = tid >> 5, lane = tid & 31;
    const int qh  = tid >> 7;          // PV: query half (8 queries)
    const int ts  = (tid >> 4) & 7;    // PV: token slice (8 tokens)

    float4 kreg[4], vreg[4];

    // prologue: gather tile 0 into registers (8 independent LDG.128)
    {
        const int nb = cbase >> 4;
        #pragma unroll
        for (int k = 0; k < 4; k++) {
            const float *kb, *vb; int st;
            block_base(k_pool, v_pool, block_ids, is64, nb + k, h, kb, vb, st);
            kreg[k] = *(const float4*)(kb + off * st + f);
            vreg[k] = *(const float4*)(vb + off * st + f);
        }
    }

    ull acc[8][2];
    #pragma unroll
    for (int qi = 0; qi < 8; qi++) { acc[qi][0] = pack2(0.f, 0.f); acc[qi][1] = acc[qi][0]; }

    for (int tile = 0; tile < NTILES; tile++) {
        __syncthreads();   // previous tile's consumers done (also covers Qs on tile 0)

        // stage registers -> smem
        #pragma unroll
        for (int k = 0; k < 4; k++) {
            int tt = k * 16 + off;
            *(float4*)&Ks[tt * KSTRIDE + f] = kreg[k];
            *(float4*)&Vs[tt * HD + f]      = vreg[k];
        }

        // prefetch next tile (loads in flight across the whole compute phase)
        if (tile < NTILES - 1) {
            const int nb = (cbase >> 4) + (tile + 1) * 4;
            #pragma unroll
            for (int k = 0; k < 4; k++) {
                const float *kb, *vb; int st;
                block_base(k_pool, v_pool, block_ids, is64, nb + k, h, kb, vb, st);
                kreg[k] = *(const float4*)(kb + off * st + f);
                vreg[k] = *(const float4*)(vb + off * st + f);
            }
        }
        __syncthreads();   // tile data visible

        // ---- QK (FFMA2): thread -> (token, 4 queries) ----
        {
            ull a0 = pack2(0.f, 0.f), a1 = a0, a2 = a0, a3 = a0;
            const ulonglong2* krow = (const ulonglong2*)&Ks[tok * KSTRIDE];
            const ulonglong2* q0r  = (const ulonglong2*)&Qs[(qg * 4 + 0) * HD];
            const ulonglong2* q1r  = (const ulonglong2*)&Qs[(qg * 4 + 1) * HD];
            const ulonglong2* q2r  = (const ulonglong2*)&Qs[(qg * 4 + 2) * HD];
            const ulonglong2* q3r  = (const ulonglong2*)&Qs[(qg * 4 + 3) * HD];
            #pragma unroll
            for (int j4 = 0; j4 < 16; j4++) {
                ulonglong2 kk = krow[j4];
                ulonglong2 q0 = q0r[j4], q1 = q1r[j4], q2 = q2r[j4], q3 = q3r[j4];
                a0 = ffma2(kk.x, q0.x, ffma2(kk.y, q0.y, a0));
                a1 = ffma2(kk.x, q1.x, ffma2(kk.y, q1.y, a1));
                a2 = ffma2(kk.x, q2.x, ffma2(kk.y, q2.y, a2));
                a3 = ffma2(kk.x, q3.x, ffma2(kk.y, q3.y, a3));
            }
            float2 u0 = unpack2(a0), u1 = unpack2(a1), u2 = unpack2(a2), u3 = unpack2(a3);
            float s0 = u0.x + u0.y, s1 = u1.x + u1.y, s2 = u2.x + u2.y, s3 = u3.x + u3.y;
            const int t0 = cbase + tile * TB;
            const int t  = t0 + tok;
            if (t0 + TB - 1 > START_POS) {   // only last tile of last chunk
                if (t > START_POS + qg * 4 + 0) s0 = -1e30f;
                if (t > START_POS + qg * 4 + 1) s1 = -1e30f;
                if (t > START_POS + qg * 4 + 2) s2 = -1e30f;
                if (t > START_POS + qg * 4 + 3) s3 = -1e30f;
            }
            Ps[(qg * 4 + 0) * TB + tok] = s0;
            Ps[(qg * 4 + 1) * TB + tok] = s1;
            Ps[(qg * 4 + 2) * TB + tok] = s2;
            Ps[(qg * 4 + 3) * TB + tok] = s3;
        }
        __syncthreads();

        // ---- online softmax: warp w handles queries 2w, 2w+1 ----
        #pragma unroll
        for (int qi = 0; qi < 2; qi++) {
            int q = wrp * 2 + qi;
            float v0 = Ps[q * TB + lane];
            float v1 = Ps[q * TB + 32 + lane];
            float mx = fmaxf(v0, v1);
            #pragma unroll
            for (int s = 16; s >= 1; s >>= 1) mx = fmaxf(mx, __shfl_xor_sync(0xffffffffu, mx, s));
            float oldm = sm_m[q];
            float nm = fmaxf(oldm, mx);
            float e0 = __expf(v0 - nm), e1 = __expf(v1 - nm);
            Ps[q * TB + lane]      = e0;
            Ps[q * TB + 32 + lane] = e1;
            float ls = e0 + e1;
            #pragma unroll
            for (int s = 16; s >= 1; s >>= 1) ls += __shfl_xor_sync(0xffffffffu, ls, s);
            if (lane == 0) {
                float cr = __expf(oldm - nm);
                sm_c[q] = cr;
                sm_m[q] = nm;
                sm_l[q] = sm_l[q] * cr + ls;
            }
        }
        __syncthreads();

        // ---- PV (FFMA2): thread -> (8 queries qh*8.., 4 cols f..f+3, tokens ts*8..+7) ----
        {
            #pragma unroll
            for (int qi = 0; qi < 8; qi++) {
                float cr = sm_c[qh * 8 + qi];
                ull crp = pack2(cr, cr);
                acc[qi][0] = fmul2(acc[qi][0], crp);
                acc[qi][1] = fmul2(acc[qi][1], crp);
            }
            #pragma unroll
            for (int g = 0; g < 2; g++) {
                ulonglong2 vj[4];
                #pragma unroll
                for (int j = 0; j < 4; j++)
                    vj[j] = *(const ulonglong2*)&Vs[(ts * 8 + g * 4 + j) * HD + f];
                #pragma unroll
                for (int qi = 0; qi < 8; qi++) {
                    float4 p = *(const float4*)&Ps[(qh * 8 + qi) * TB + ts * 8 + g * 4];
                    ull p0 = pack2(p.x, p.x), p1 = pack2(p.y, p.y);
                    ull p2 = pack2(p.z, p.z), p3 = pack2(p.w, p.w);
                    acc[qi][0] = ffma2(p0, vj[0].x, acc[qi][0]);
                    acc[qi][1] = ffma2(p0, vj[0].y, acc[qi][1]);
                    acc[qi][0] = ffma2(p1, vj[1].x, acc[qi][0]);
                    acc[qi][1] = ffma2(p1, vj[1].y, acc[qi][1]);
                    acc[qi][0] = ffma2(p2, vj[2].x, acc[qi][0]);
                    acc[qi][1] = ffma2(p2, vj[2].y, acc[qi][1]);
                    acc[qi][0] = ffma2(p3, vj[3].x, acc[qi][0]);
                    acc[qi][1] = ffma2(p3, vj[3].y, acc[qi][1]);
                }
            }
        }
    }

    // ---- tree-reduce accumulators across the 8 token slices (one-time) ----
    __syncthreads();
    ull* R = (ull*)Ks;   // reuse: 128 slots x 16 ull = 16KB <= Ks
    #pragma unroll
    for (int s = 4; s >= 1; s >>= 1) {
        if (ts >= s && ts < 2 * s) {
            int slot = (((ts - s) * 2 + qh) * 16 + fg) * 16;
            #pragma unroll
            for (int qi = 0; qi < 8; qi++) {
                R[slot + qi * 2]     = acc[qi][0];
                R[slot + qi * 2 + 1] = acc[qi][1];
            }
        }
        __syncthreads();
        if (ts < s) {
            int slot = ((ts * 2 + qh) * 16 + fg) * 16;
            #pragma unroll
            for (int qi = 0; qi < 8; qi++) {
                acc[qi][0] = fadd2(acc[qi][0], R[slot + qi * 2]);
                acc[qi][1] = fadd2(acc[qi][1], R[slot + qi * 2 + 1]);
            }
        }
        __syncthreads();
    }

    // ---- write partials ----
    if (ts == 0) {
        const int pbase = (h * NC + cidx) * L_Q;
        #pragma unroll
        for (int qi = 0; qi < 8; qi++) {
            int q = qh * 8 + qi;
            float2 a = unpack2(acc[qi][0]), b = unpack2(acc[qi][1]);
            *(float4*)&g_part[(pbase + q) * HD + f] = make_float4(a.x, a.y, b.x, b.y);
        }
    }
    if (tid < 16) {
        const int pbase = (h * NC + cidx) * L_Q;
        g_m[pbase + tid] = sm_m[tid];
        g_s[pbase + tid] = sm_l[tid];
    }
}

// ---------------- combine split-KV partials ----------------
// grid (H, L), 256 threads: (j = tid&63) x (chunk-group = tid>>6 of 4 chunks)
__global__ void combine_kernel() {
    __shared__ float red[4][64];
    const int h = blockIdx.x;
    const int l = blockIdx.y;
    const int tid = threadIdx.x;
    const int j  = tid & 63;
    const int cg = tid >> 6;

    // all threads compute the 16 merge weights (broadcast loads, L2-hot)
    float m[NC]; float M = -1e30f;
    #pragma unroll
    for (int c = 0; c < NC; c++) { m[c] = g_m[(h * NC + c) * L_Q + l]; M = fmaxf(M, m[c]); }
    float w[NC]; float S = 0.f;
    #pragma unroll
    for (int c = 0; c < NC; c++) {
        w[c] = __expf(m[c] - M);
        S += g_s[(h * NC + c) * L_Q + l] * w[c];
    }

    float acc = 0.f;
    #pragma unroll
    for (int ci = 0; ci < 4; ci++) {
        int c = cg * 4 + ci;
        acc += g_part[((h * NC + c) * L_Q + l) * HD + j] * w[c];
    }
    red[cg][j] = acc;
    __syncthreads();
    if (cg == 0) {
        float tot = red[0][j] + red[1][j] + red[2][j] + red[3][j];
        g_ao[l * D_MODEL + h * HD + j] = tot / S;
    }
}

// ---------------- output projection: out += g_ao @ W_proj (split-K atomics) ----
// grid (8, 16): j-tiles of 128, i-chunks of 64. 128 threads.
__global__ void gemm_proj(const float* __restrict__ W, float* __restrict__ out) {
    __shared__ float as[L_Q][64];
    const int tid = threadIdx.x;
    const int i0 = blockIdx.y * 64;
    for (int idx = tid; idx < L_Q * 64; idx += 128) {
        int l = idx >> 6, ii = idx & 63;
        as[l][ii] = g_ao[l * D_MODEL + i0 + ii];
    }
    __syncthreads();
    const int j = blockIdx.x * 128 + tid;
    float acc[L_Q] = {};
    #pragma unroll 16
    for (int ii = 0; ii < 64; ii++) {
        float w = W[(long)(i0 + ii) * D_MODEL + j];
        #pragma unroll
        for (int l = 0; l < L_Q; l++) acc[l] = fmaf(as[l][ii], w, acc[l]);
    }
    #pragma unroll
    for (int l = 0; l < L_Q; l++) atomicAdd(&out[l * D_MODEL + j], acc[l]);
}

// ---------------- launch ----------------
extern "C" void kernel_launch(void* const* d_in, const int* in_sizes, int n_in,
                              void* d_out, int out_size) {
    const float* x       = (const float*)d_in[0];
    const float* k_pool  = (const float*)d_in[1];
    const float* v_pool  = (const float*)d_in[2];
    const float* W_attn  = (const float*)d_in[3];
    const float* b_attn  = (const float*)d_in[4];
    const float* W_proj  = (const float*)d_in[5];
    const float* b_proj  = (const float*)d_in[6];
    const void*  blk_ids = (const void*)d_in[7];
    float* out = (float*)d_out;

    init_kernel<<<(L_Q * 3 * D_MODEL + 255) / 256, 256>>>(b_attn, b_proj, out);
    gemm_qkv<<<dim3(24, 16), 128>>>(x, W_attn);
    attn_kernel<<<dim3(NC, H_HEADS), 256>>>(k_pool, v_pool, blk_ids);
    combine_kernel<<<dim3(H_HEADS, L_Q), 256>>>();
    gemm_proj<<<dim3(8, 16), 128>>>(W_proj, out);
}